// round 13
// baseline (speedup 1.0000x reference)
#include <cuda_runtime.h>
#include <math.h>

// Problem constants
#define BB 2048     // batch (samples == queries)
#define RR 64       // receptors
#define TILES 16    // BB / 128
#define NPAIRS 136  // TILES*(TILES+1)/2
#define QT 16       // query tiles for logsum
#define CB 128      // row-chunks for Gram/colsum partials
#define CROWS 16    // rows per chunk (CB*CROWS == BB)
#define GRB 32      // gram-reduce blocks (32 x 128 threads = 4096 cells)

// -------- device scratch (static: no allocations allowed) --------
__device__ float g_act_t[RR * BB];         // column-major transpose of act (unscaled)
__device__ float g_dnorm[RR];              // invh / (B * sqrt(2*pi))  (written by kde diag(0,0) blocks)
__device__ float g_mean[RR];               // (written by kde diag(0,0) blocks)
__device__ float g_colsum[CB * RR];        // per-chunk column sums
__device__ float g_part[TILES * RR * BB];  // [slot][r][q] density partial sums (8MB)
__device__ float g_ent_partial[QT * RR];   // per-(qtile, r) sum of log(density+eps)
__device__ float g_gram[CB * RR * RR];     // RAW (uncentered) Gram partials (2MB)
__device__ float g_cov_partial[GRB];       // per-block sum of squared off-diag cov

// Hardware exp2: single MUFU.EX2 (ftz on tiny results — harmless here).
__device__ __forceinline__ float ex2(float x) {
    float y;
    asm("ex2.approx.ftz.f32 %0, %1;" : "=f"(y) : "f"(x));
    return y;
}

// ---------------------------------------------------------------------------
// Stage 1: per-chunk raw Gram (64x64) + per-chunk column sums + transposed
// copy of the chunk into column-major g_act_t. All from one coalesced shared
// tile; no strided global reads anywhere in the pipeline.
// ---------------------------------------------------------------------------
__global__ void prep_kernel(const float* __restrict__ act) {
    __shared__ float ch[CROWS * RR];   // 16 x 64 raw rows (4KB)
    const int b   = blockIdx.x;        // 0..CB-1
    const int tid = threadIdx.x;       // 256

    // coalesced float4 load: 256 threads x 1 float4 = 1024 floats
    reinterpret_cast<float4*>(ch)[tid] =
        reinterpret_cast<const float4*>(act + b * CROWS * RR)[tid];
    __syncthreads();

    // transposed write: i = r*16 + s  ->  g_act_t[r*BB + b*16 + s]
    #pragma unroll
    for (int i = tid; i < CROWS * RR; i += 256) {
        const int r = i >> 4;
        const int s = i & 15;
        g_act_t[r * BB + b * CROWS + s] = ch[s * RR + r];
    }

    // per-chunk column sums (threads 0..63)
    if (tid < RR) {
        float cs = 0.f;
        #pragma unroll
        for (int s = 0; s < CROWS; ++s) cs += ch[s * RR + tid];
        g_colsum[b * RR + tid] = cs;
    }

    const int ti = tid & 15;   // column-group i
    const int tj = tid >> 4;   // column-group j
    float acc[4][4];
    #pragma unroll
    for (int y = 0; y < 4; ++y)
        #pragma unroll
        for (int x = 0; x < 4; ++x) acc[y][x] = 0.f;

    const float4* __restrict__ s4 = reinterpret_cast<const float4*>(ch);
    #pragma unroll
    for (int s = 0; s < CROWS; ++s) {
        const float4 ai = s4[s * 16 + ti];
        const float4 aj = s4[s * 16 + tj];
        const float av[4] = { ai.x, ai.y, ai.z, ai.w };
        const float bv[4] = { aj.x, aj.y, aj.z, aj.w };
        #pragma unroll
        for (int y = 0; y < 4; ++y)
            #pragma unroll
            for (int x = 0; x < 4; ++x)
                acc[y][x] += av[x] * bv[y];
    }

    float* __restrict__ gp = g_gram + b * RR * RR;
    #pragma unroll
    for (int y = 0; y < 4; ++y)
        #pragma unroll
        for (int x = 0; x < 4; ++x)
            gp[(tj * 4 + y) * RR + (ti * 4 + x)] = acc[y][x];
}

// ---------------------------------------------------------------------------
// Stage 2: symmetric KDE with DISTRIBUTED stats prologue.
// Every block computes k[r] itself from the 128 colsum + 128 Gram-diagonal
// partials (1 LDG each per thread, 7-stage shared tree) — identical values,
// identical order in every block => identical k, fully deterministic. The
// prologue runs on LSU/FMA pipes and is hidden by co-resident blocks'
// MUFU mainloops, so the kde wall time stays at its MUFU floor.
// The (pair 0 = diag tile 0, r) block uniquely writes g_mean/g_dnorm for
// the reduce stage. This removes the separate finalize kernel + one gap.
// ---------------------------------------------------------------------------
__global__ void kde_sym_kernel() {
    const int r = blockIdx.y;
    // map linear pair index -> (I, J), I <= J
    int I = 0, rem = blockIdx.x;
    while (rem >= TILES - I) { rem -= TILES - I; ++I; }
    const int J = I + rem;

    const int tid  = threadIdx.x;   // 128
    const int lane = tid & 31;
    const int w    = tid >> 5;

    __shared__ float shc[4][128];   // stats reduce now, column-merge later

    // ---- stats prologue: thread t owns chunk t (CB == 128) ----
    shc[0][tid] = g_colsum[tid * RR + r];
    shc[1][tid] = g_gram[tid * (RR * RR) + r * RR + r];  // chunk diag = sum x^2
    __syncthreads();
    for (int o = 64; o > 0; o >>= 1) {
        if (tid < o) {
            shc[0][tid] += shc[0][tid + o];
            shc[1][tid] += shc[1][tid + o];
        }
        __syncthreads();
    }
    const float mean = shc[0][0] * (1.0f / BB);
    const float ssc  = shc[1][0] - (float)BB * mean * mean;
    const float var  = ssc * (1.0f / (BB - 1));
    const float stdv = sqrtf(var);
    // BANDWIDTH_FACTOR * std * B^(-0.2);  2048^(-0.2) = 0.21763764
    const float h    = fmaxf(1.06f * stdv * 0.21763764f, 1e-4f);
    const float invh = 1.0f / h;
    // sqrt(0.5 * log2(e)) so exp(-0.5*u^2) == 2^{-(u')^2}
    const float kk   = invh * 0.84932184f;

    if (blockIdx.x == 0 && tid == 0) {   // unique writer: diag tile (0,0)
        g_dnorm[r] = invh * (1.0f / (2048.0f * 2.5066282746310002f));
        g_mean[r]  = mean;
    }
    __syncthreads();   // release shc for reuse below

    // ---- KDE mainloop ----
    const float* __restrict__ col = g_act_t + r * BB;

    float4 sv = reinterpret_cast<const float4*>(col + J * 128)[lane];
    sv.x *= kk; sv.y *= kk; sv.z *= kk; sv.w *= kk;
    float aqc  = col[I * 128 + tid] * kk;
    float rowc = 0.f;
    float4 ca  = make_float4(0.f, 0.f, 0.f, 0.f);

    const unsigned FULL = 0xFFFFFFFFu;

    if (I != J) {
        #pragma unroll 8
        for (int m = 0; m < 32; ++m) {
            float u, v0, v1, v2, v3;
            u = aqc - sv.x; v0 = ex2(-u * u);
            u = aqc - sv.y; v1 = ex2(-u * u);
            u = aqc - sv.z; v2 = ex2(-u * u);
            u = aqc - sv.w; v3 = ex2(-u * u);
            ca.x += v0; ca.y += v1; ca.z += v2; ca.w += v3;
            rowc += (v0 + v1) + (v2 + v3);
            aqc  = __shfl_sync(FULL, aqc,  (lane + 1) & 31);
            rowc = __shfl_sync(FULL, rowc, (lane + 1) & 31);
        }

        reinterpret_cast<float4*>(shc[w])[lane] = ca;
        __syncthreads();
        const float ct = shc[0][tid] + shc[1][tid] + shc[2][tid] + shc[3][tid];

        g_part[I * (RR * BB) + r * BB + J * 128 + tid] = ct;    // tile-J densities
        g_part[J * (RR * BB) + r * BB + I * 128 + tid] = rowc;  // tile-I densities
    } else {
        #pragma unroll 8
        for (int m = 0; m < 32; ++m) {
            float u, v0, v1, v2, v3;
            u = aqc - sv.x; v0 = ex2(-u * u);
            u = aqc - sv.y; v1 = ex2(-u * u);
            u = aqc - sv.z; v2 = ex2(-u * u);
            u = aqc - sv.w; v3 = ex2(-u * u);
            rowc += (v0 + v1) + (v2 + v3);
            aqc  = __shfl_sync(FULL, aqc,  (lane + 1) & 31);
            rowc = __shfl_sync(FULL, rowc, (lane + 1) & 31);
        }
        g_part[I * (RR * BB) + r * BB + I * 128 + tid] = rowc;
    }
}

// ---------------------------------------------------------------------------
// Stage 3 (fused): blocks [0, QT*RR)            -> logsum of densities
//                  blocks [QT*RR, QT*RR + GRB)  -> Gram fold + mean-correct +
//                                                  off-diag square-sum
// ---------------------------------------------------------------------------
__global__ void reduce_kernel() {
    __shared__ float red[128];
    const int tid = threadIdx.x;   // 128

    if (blockIdx.x < QT * RR) {
        // ---------------- logsum half ----------------
        const int r  = blockIdx.x >> 4;
        const int qt = blockIdx.x & 15;
        const int q  = qt * 128 + tid;

        float s = 0.f;
        #pragma unroll
        for (int slot = 0; slot < TILES; ++slot)
            s += g_part[slot * (RR * BB) + r * BB + q];

        const float dens = s * g_dnorm[r];
        red[tid] = logf(dens + 1e-8f);
        __syncthreads();
        for (int o = 64; o > 0; o >>= 1) {
            if (tid < o) red[tid] += red[tid + o];
            __syncthreads();
        }
        if (tid == 0) g_ent_partial[qt * RR + r] = red[0];
    } else {
        // ---------------- Gram-reduce half ----------------
        const int gb = blockIdx.x - QT * RR;   // 0..GRB-1
        const int p  = gb * 128 + tid;         // cell in 64x64
        const int i  = p & (RR - 1);
        const int j  = p >> 6;

        float g = 0.f;
        #pragma unroll 16
        for (int b = 0; b < CB; ++b) g += g_gram[b * RR * RR + p];

        // centered Gram: sum((x_i - m_i)(x_j - m_j)) = raw - B*m_i*m_j
        g -= (float)BB * g_mean[i] * g_mean[j];

        float cs = 0.f;
        if (i != j) {
            const float c = g * (1.0f / (BB - 1));
            cs = c * c;
        }
        red[tid] = cs;
        __syncthreads();
        for (int o = 64; o > 0; o >>= 1) {
            if (tid < o) red[tid] += red[tid + o];
            __syncthreads();
        }
        if (tid == 0) g_cov_partial[gb] = red[0];
    }
}

// ---------------------------------------------------------------------------
// Stage 4: deterministic final combine (tiny: 1024 + 32 floats).
// ---------------------------------------------------------------------------
__global__ void final_kernel(float* __restrict__ out) {
    __shared__ float red[256];
    const int tid = threadIdx.x;  // 256 threads

    // 1024 entropy partials as 256 float4 loads (MLP-friendly)
    const float4 e4 = reinterpret_cast<const float4*>(g_ent_partial)[tid];
    float es = (e4.x + e4.y) + (e4.z + e4.w);

    float cs = 0.f;
    if (tid < GRB) cs = g_cov_partial[tid];

    red[tid] = es * (1.0f / (float)(BB * RR)) + cs;
    __syncthreads();
    for (int o = 128; o > 0; o >>= 1) {
        if (tid < o) red[tid] += red[tid + o];
        __syncthreads();
    }
    if (tid == 0) out[0] = red[0];
}

// ---------------------------------------------------------------------------
extern "C" void kernel_launch(void* const* d_in, const int* in_sizes, int n_in,
                              void* d_out, int out_size) {
    const float* act = (const float*)d_in[0];
    float* out = (float*)d_out;
    (void)in_sizes; (void)n_in; (void)out_size;

    prep_kernel<<<CB, 256>>>(act);
    kde_sym_kernel<<<dim3(NPAIRS, RR), 128>>>();
    reduce_kernel<<<QT * RR + GRB, 128>>>();
    final_kernel<<<1, 256>>>(out);
}

// round 14
// speedup vs baseline: 1.1411x; 1.1411x over previous
#include <cuda_runtime.h>
#include <math.h>

// Problem constants
#define BB 2048     // batch (samples == queries)
#define RR 64       // receptors
#define TILES 16    // BB / 128
#define NPAIRS 136  // TILES*(TILES+1)/2
#define QT 16       // query tiles for logsum
#define CB 128      // row-chunks for Gram/colsum partials
#define CROWS 16    // rows per chunk (CB*CROWS == BB)
#define GRB 32      // gram-reduce blocks (32 x 128 threads = 4096 cells)

// -------- device scratch (static: no allocations allowed) --------
__device__ float g_act_t[RR * BB];         // column-major transpose of act (unscaled)
__device__ float g_k[RR];                  // invh * sqrt(0.5*log2e) per receptor
__device__ float g_dnorm[RR];              // invh / (B * sqrt(2*pi))
__device__ float g_mean[RR];
__device__ float g_colsum[CB * RR];        // per-chunk column sums
__device__ float g_part[TILES * RR * BB];  // [slot][r][q] density partial sums (8MB)
__device__ float g_gram[CB * RR * RR];     // RAW (uncentered) Gram partials (2MB)

// Hardware exp2: single MUFU.EX2 (ftz on tiny results — harmless here).
__device__ __forceinline__ float ex2(float x) {
    float y;
    asm("ex2.approx.ftz.f32 %0, %1;" : "=f"(y) : "f"(x));
    return y;
}

// ---------------------------------------------------------------------------
// Stage 1: per-chunk raw Gram (64x64) + per-chunk column sums + transposed
// copy of the chunk into column-major g_act_t. All from one coalesced shared
// tile; the only strided traffic in the whole pipeline is this kernel's
// transposed SMEM->GMEM write (O(data), 64B granular, cheap).
// Block 0 also zeroes out[0] (poisoned 0xAA by the harness) for the
// accumulate-style final combine in reduce_kernel.
// ---------------------------------------------------------------------------
__global__ void prep_kernel(const float* __restrict__ act, float* __restrict__ out) {
    __shared__ float ch[CROWS * RR];   // 16 x 64 raw rows (4KB)
    const int b   = blockIdx.x;        // 0..CB-1
    const int tid = threadIdx.x;       // 256

    if (b == 0 && tid == 0) out[0] = 0.f;

    // coalesced float4 load: 256 threads x 1 float4 = 1024 floats
    reinterpret_cast<float4*>(ch)[tid] =
        reinterpret_cast<const float4*>(act + b * CROWS * RR)[tid];
    __syncthreads();

    // transposed write: i = r*16 + s  ->  g_act_t[r*BB + b*16 + s]
    #pragma unroll
    for (int i = tid; i < CROWS * RR; i += 256) {
        const int r = i >> 4;
        const int s = i & 15;
        g_act_t[r * BB + b * CROWS + s] = ch[s * RR + r];
    }

    // per-chunk column sums (threads 0..63)
    if (tid < RR) {
        float cs = 0.f;
        #pragma unroll
        for (int s = 0; s < CROWS; ++s) cs += ch[s * RR + tid];
        g_colsum[b * RR + tid] = cs;
    }

    const int ti = tid & 15;   // column-group i
    const int tj = tid >> 4;   // column-group j
    float acc[4][4];
    #pragma unroll
    for (int y = 0; y < 4; ++y)
        #pragma unroll
        for (int x = 0; x < 4; ++x) acc[y][x] = 0.f;

    const float4* __restrict__ s4 = reinterpret_cast<const float4*>(ch);
    #pragma unroll
    for (int s = 0; s < CROWS; ++s) {
        const float4 ai = s4[s * 16 + ti];
        const float4 aj = s4[s * 16 + tj];
        const float av[4] = { ai.x, ai.y, ai.z, ai.w };
        const float bv[4] = { aj.x, aj.y, aj.z, aj.w };
        #pragma unroll
        for (int y = 0; y < 4; ++y)
            #pragma unroll
            for (int x = 0; x < 4; ++x)
                acc[y][x] += av[x] * bv[y];
    }

    float* __restrict__ gp = g_gram + b * RR * RR;
    #pragma unroll
    for (int y = 0; y < 4; ++y)
        #pragma unroll
        for (int x = 0; x < 4; ++x)
            gp[(tj * 4 + y) * RR + (ti * 4 + x)] = acc[y][x];
}

// ---------------------------------------------------------------------------
// Stage 1b: finalize per-receptor stats from the CB partials (64 blocks —
// the strided partial reads happen exactly once, here, not per kde block).
// var = (sumsq - B*mean^2)/(B-1): raw-moment form; validated rel_err 3.6e-7.
// ---------------------------------------------------------------------------
__global__ void finalize_kernel() {
    __shared__ float rs[CB], rq[CB];
    const int r = blockIdx.x;      // 0..RR-1
    const int t = threadIdx.x;     // 128 == CB

    rs[t] = g_colsum[t * RR + r];
    rq[t] = g_gram[t * RR * RR + r * RR + r];   // chunk diagonal = sum x^2
    __syncthreads();
    for (int o = 64; o > 0; o >>= 1) {
        if (t < o) { rs[t] += rs[t + o]; rq[t] += rq[t + o]; }
        __syncthreads();
    }
    if (t == 0) {
        const float mean = rs[0] * (1.0f / BB);
        const float ssc  = rq[0] - (float)BB * mean * mean;
        const float var  = ssc * (1.0f / (BB - 1));
        const float stdv = sqrtf(var);
        // BANDWIDTH_FACTOR * std * B^(-0.2);  2048^(-0.2) = 0.21763764
        const float h    = fmaxf(1.06f * stdv * 0.21763764f, 1e-4f);
        const float invh = 1.0f / h;
        // sqrt(0.5 * log2(e)) so exp(-0.5*u^2) == 2^{-(u')^2}
        g_k[r]     = invh * 0.84932184f;
        g_dnorm[r] = invh * (1.0f / (2048.0f * 2.5066282746310002f));
        g_mean[r]  = mean;
    }
}

// ---------------------------------------------------------------------------
// Stage 2: symmetric KDE from the column-major transpose (coalesced float4
// loads, L2-resident), scaling by g_k[r] inline at load. Block = (tile-pair,
// receptor), 128 threads. Each lane owns 4 tile-J columns in registers;
// (query, row accumulator) rotates across the 32 lanes via SHFL. Off-diag
// pairs: each exp serves both a row (tile-I) and a column (tile-J) density.
// ---------------------------------------------------------------------------
__global__ void kde_sym_kernel() {
    const int r = blockIdx.y;
    // map linear pair index -> (I, J), I <= J
    int I = 0, rem = blockIdx.x;
    while (rem >= TILES - I) { rem -= TILES - I; ++I; }
    const int J = I + rem;

    const int tid  = threadIdx.x;   // 128
    const int lane = tid & 31;
    const int w    = tid >> 5;

    const float kk = g_k[r];
    const float* __restrict__ col = g_act_t + r * BB;

    float4 sv = reinterpret_cast<const float4*>(col + J * 128)[lane];
    sv.x *= kk; sv.y *= kk; sv.z *= kk; sv.w *= kk;
    float aqc  = col[I * 128 + tid] * kk;
    float rowc = 0.f;
    float4 ca  = make_float4(0.f, 0.f, 0.f, 0.f);

    const unsigned FULL = 0xFFFFFFFFu;

    if (I != J) {
        #pragma unroll 8
        for (int m = 0; m < 32; ++m) {
            float u, v0, v1, v2, v3;
            u = aqc - sv.x; v0 = ex2(-u * u);
            u = aqc - sv.y; v1 = ex2(-u * u);
            u = aqc - sv.z; v2 = ex2(-u * u);
            u = aqc - sv.w; v3 = ex2(-u * u);
            ca.x += v0; ca.y += v1; ca.z += v2; ca.w += v3;
            rowc += (v0 + v1) + (v2 + v3);
            aqc  = __shfl_sync(FULL, aqc,  (lane + 1) & 31);
            rowc = __shfl_sync(FULL, rowc, (lane + 1) & 31);
        }

        __shared__ float shc[4][128];
        reinterpret_cast<float4*>(shc[w])[lane] = ca;
        __syncthreads();
        const float ct = shc[0][tid] + shc[1][tid] + shc[2][tid] + shc[3][tid];

        g_part[I * (RR * BB) + r * BB + J * 128 + tid] = ct;    // tile-J densities
        g_part[J * (RR * BB) + r * BB + I * 128 + tid] = rowc;  // tile-I densities
    } else {
        #pragma unroll 8
        for (int m = 0; m < 32; ++m) {
            float u, v0, v1, v2, v3;
            u = aqc - sv.x; v0 = ex2(-u * u);
            u = aqc - sv.y; v1 = ex2(-u * u);
            u = aqc - sv.z; v2 = ex2(-u * u);
            u = aqc - sv.w; v3 = ex2(-u * u);
            rowc += (v0 + v1) + (v2 + v3);
            aqc  = __shfl_sync(FULL, aqc,  (lane + 1) & 31);
            rowc = __shfl_sync(FULL, rowc, (lane + 1) & 31);
        }
        g_part[I * (RR * BB) + r * BB + I * 128 + tid] = rowc;
    }
}

// ---------------------------------------------------------------------------
// Stage 3 (fused, FINAL): blocks [0, QT*RR)     -> logsum of densities
//                         blocks [QT*RR, +GRB)  -> Gram fold + mean-correct +
//                                                  off-diag square-sum
// Each block fire-and-forget atomicAdd's its already-weighted partial into
// out[0] (zeroed by prep). One REDG per block, no fence, no ticket — the
// 1056 single-address adds cost <1K cycles of L2 atomic ALU, overlapped.
// total = (1/(B*R)) * sum log(dens+eps) + sum_offdiag cov^2.
// ---------------------------------------------------------------------------
__global__ void reduce_kernel(float* __restrict__ out) {
    __shared__ float red[128];
    const int tid = threadIdx.x;   // 128

    if (blockIdx.x < QT * RR) {
        // ---------------- logsum half ----------------
        const int r  = blockIdx.x >> 4;
        const int qt = blockIdx.x & 15;
        const int q  = qt * 128 + tid;

        float s = 0.f;
        #pragma unroll
        for (int slot = 0; slot < TILES; ++slot)
            s += g_part[slot * (RR * BB) + r * BB + q];

        const float dens = s * g_dnorm[r];
        red[tid] = logf(dens + 1e-8f);
        __syncthreads();
        for (int o = 64; o > 0; o >>= 1) {
            if (tid < o) red[tid] += red[tid + o];
            __syncthreads();
        }
        if (tid == 0) atomicAdd(out, red[0] * (1.0f / (float)(BB * RR)));
    } else {
        // ---------------- Gram-reduce half ----------------
        const int gb = blockIdx.x - QT * RR;   // 0..GRB-1
        const int p  = gb * 128 + tid;         // cell in 64x64
        const int i  = p & (RR - 1);
        const int j  = p >> 6;

        float g = 0.f;
        #pragma unroll 16
        for (int b = 0; b < CB; ++b) g += g_gram[b * RR * RR + p];

        // centered Gram: sum((x_i - m_i)(x_j - m_j)) = raw - B*m_i*m_j
        g -= (float)BB * g_mean[i] * g_mean[j];

        float cs = 0.f;
        if (i != j) {
            const float c = g * (1.0f / (BB - 1));
            cs = c * c;
        }
        red[tid] = cs;
        __syncthreads();
        for (int o = 64; o > 0; o >>= 1) {
            if (tid < o) red[tid] += red[tid + o];
            __syncthreads();
        }
        if (tid == 0) atomicAdd(out, red[0]);
    }
}

// ---------------------------------------------------------------------------
extern "C" void kernel_launch(void* const* d_in, const int* in_sizes, int n_in,
                              void* d_out, int out_size) {
    const float* act = (const float*)d_in[0];
    float* out = (float*)d_out;
    (void)in_sizes; (void)n_in; (void)out_size;

    prep_kernel<<<CB, 256>>>(act, out);
    finalize_kernel<<<RR, CB>>>();
    kde_sym_kernel<<<dim3(NPAIRS, RR), 128>>>();
    reduce_kernel<<<QT * RR + GRB, 128>>>(out);
}